// round 11
// baseline (speedup 1.0000x reference)
#include <cuda_runtime.h>

// Shapes: depth_map/x_ray [8,1,512,512] fp32 -> out [8,1,128,128,128] fp32
#define NB   8
#define INHW 512
#define RHW  128   // resized H=W
#define ND   128   // depth bins

// Intermediate buffers (device globals: allocation-free scratch)
__device__ float g_xr[NB * RHW * RHW];
__device__ int   g_di[NB * RHW * RHW];

// ---------------------------------------------------------------------------
// Kernel 1: jax.image.resize(bilinear, antialias=True) 512->128 both arrays,
// plus depth->index conversion. Block = 4 output rows (h) of one batch b,
// 512 threads = (r = tid>>7 -> row, wt = tid&127 -> float4 column group).
// The 8-tap vertical windows of adjacent output rows overlap by 4 input rows;
// those re-reads hit L1 within the block (cuts L2 read traffic ~38%).
// Raw triangle weights {1,3,5,7,7,5,3,1}/8, normalized by in-range weight sum.
// ---------------------------------------------------------------------------
__global__ __launch_bounds__(512) void resize_kernel(const float* __restrict__ depth,
                                                     const float* __restrict__ xray) {
    const int tid = threadIdx.x;
    const int r   = tid >> 7;
    const int wt  = tid & 127;
    const int h   = blockIdx.x * 4 + r;
    const int b   = blockIdx.y;

    __shared__ float tmpd[4][INHW];
    __shared__ float tmpx[4][INHW];

    const float RW[8] = {0.125f, 0.375f, 0.625f, 0.875f,
                         0.875f, 0.625f, 0.375f, 0.125f};

    float4 ad = make_float4(0.f, 0.f, 0.f, 0.f);
    float4 ax = make_float4(0.f, 0.f, 0.f, 0.f);
    float wsv = 0.f;

    #pragma unroll
    for (int t = 0; t < 8; ++t) {
        int j = 4 * h - 2 + t;                 // input row (uniform per warp)
        if ((unsigned)j >= (unsigned)INHW) continue;
        float wv = RW[t];
        wsv += wv;
        const float4* drow = (const float4*)(depth + ((size_t)b * INHW + j) * INHW);
        const float4* xrow = (const float4*)(xray  + ((size_t)b * INHW + j) * INHW);
        float4 dv = drow[wt];
        float4 xv = xrow[wt];
        ad.x = fmaf(wv, dv.x, ad.x); ad.y = fmaf(wv, dv.y, ad.y);
        ad.z = fmaf(wv, dv.z, ad.z); ad.w = fmaf(wv, dv.w, ad.w);
        ax.x = fmaf(wv, xv.x, ax.x); ax.y = fmaf(wv, xv.y, ax.y);
        ax.z = fmaf(wv, xv.z, ax.z); ax.w = fmaf(wv, xv.w, ax.w);
    }
    ((float4*)tmpd[r])[wt] = ad;
    ((float4*)tmpx[r])[wt] = ax;
    __syncthreads();

    float sd = 0.f, sx = 0.f, wsh = 0.f;
    #pragma unroll
    for (int t = 0; t < 8; ++t) {
        int c = 4 * wt - 2 + t;                // input col
        if ((unsigned)c < (unsigned)INHW) {
            float wv = RW[t];
            wsh += wv;
            sd = fmaf(wv, tmpd[r][c], sd);
            sx = fmaf(wv, tmpx[r][c], sx);
        }
    }
    float inv = 1.f / (wsv * wsh);
    float dv  = sd * inv;                      // resized depth
    float xv  = sx * inv;                      // resized x_ray

    // d_idx = clip(int((depth/100)*127), 0, 127)  (truncation; depth >= 0)
    int di = (int)((dv / 100.f) * 127.f);
    di = di < 0 ? 0 : (di > ND - 1 ? ND - 1 : di);

    int idx = (b * RHW + h) * RHW + wt;
    g_xr[idx] = xv;
    g_di[idx] = di;
}

// ---------------------------------------------------------------------------
// Kernel 2: fused gaussian depth splat + 3x3x3 avg pool (/27, include_pad),
// reformulated as histogram + dense separable depth convolution:
//   s[d][w]  = sum over the 9 spatial neighbors of (h,w) of xv_n * [di_n == d]
//              (the 3x3 spatial pool folded into the histogram)
//   p[t]     = (gauss5 (*) s)[t], evaluated ONLY for t in [0,127]
//              (this IS the reference's splat-target clipping)
//   out[d]   = p[d-1] + p[d] + p[d+1], with p[-1] = p[128] = 0 (pool zero-pad)
// 1/27 is folded into the gaussian weights.
//
// Block = (h, b), 512 threads = (w = tid&127, q = tid>>7). Histogram tile is
// d-major with 3-row zero pad on each side: s[136][128] (68KB dynamic smem);
// every access by lane w hits bank w%32 -> zero conflicts everywhere.
// Scatter: q==0 threads only, 9 warp-uniform RMWs per column (vs 63 before).
// Gather: thread (w,q) computes depths [32q,32q+32) with a 5-wide sliding
// s-window: 1 LDS + 2 FMA + 4 ADD + 1 coalesced STG per output element.
// ---------------------------------------------------------------------------
#define SROWS 136           // depths -3..130 at offset +3 (rows 134/135 pad)

__global__ __launch_bounds__(512) void splat_pool_kernel(float* __restrict__ out) {
    extern __shared__ float s[];               // [SROWS][128], 69632 B
    __shared__ float sxs[3][130];
    __shared__ int   sdis[3][130];

    const int h   = blockIdx.x;
    const int b   = blockIdx.y;
    const int tid = threadIdx.x;
    const int w   = tid & 127;
    const int q   = tid >> 7;

    // Zero the histogram tile
    for (int i = tid; i < SROWS * 128; i += 512) s[i] = 0.f;

    // Cooperative halo load: 3 rows x 130 cols (zero-padded out of range)
    if (tid < 3 * 130) {
        int dh = tid / 130, wi = tid - dh * 130;
        int hh = h + dh - 1, ww = wi - 1;
        bool v = ((unsigned)hh < (unsigned)RHW) && ((unsigned)ww < (unsigned)RHW);
        int idx = (b * RHW + (v ? hh : 0)) * RHW + (v ? ww : 0);
        sxs[dh][wi]  = v ? g_xr[idx] : 0.f;
        sdis[dh][wi] = v ? g_di[idx] : 0;
    }
    __syncthreads();

    // Scatter: 9-neighbor weighted histogram per column (unique owner: q==0)
    if (q == 0) {
        #pragma unroll
        for (int dh = 0; dh < 3; ++dh) {
            #pragma unroll
            for (int dw = 0; dw < 3; ++dw) {
                float xv = sxs[dh][w + dw];    // 0 for padding -> harmless
                int   di = sdis[dh][w + dw];
                s[(di + 3) * 128 + w] += xv;
            }
        }
    }
    __syncthreads();

    // Gaussian weights with 1/27 folded in
    const float G0 = 0.037037037037037f;               // 1/27
    const float G1 = 0.0224640983967f;                 // exp(-0.5)/27
    const float G2 = 0.0050124179717f;                 // exp(-2)/27

    const int d0 = q << 5;                             // this thread's depth base

    // Prologue: sv[k] = s[d0-3+k], k=0..6  (tile row = d0+k)
    float sv[7];
    #pragma unroll
    for (int k = 0; k < 7; ++k) sv[k] = s[(d0 + k) * 128 + w];

    // p[t] = G2*(s[t-2]+s[t+2]) + G1*(s[t-1]+s[t+1]) + G0*s[t]
    float pm = fmaf(G2, sv[0] + sv[4], fmaf(G1, sv[1] + sv[3], G0 * sv[2])); // p[d0-1]
    float pc = fmaf(G2, sv[1] + sv[5], fmaf(G1, sv[2] + sv[4], G0 * sv[3])); // p[d0]
    float pn = fmaf(G2, sv[2] + sv[6], fmaf(G1, sv[3] + sv[5], G0 * sv[4])); // p[d0+1]
    if (q == 0) pm = 0.f;                              // exclude p[-1]

    // Rolling s window: s0..s4 = s[d-1 .. d+3] at loop top (d = current out)
    float s0 = sv[2], s1 = sv[3], s2 = sv[4], s3 = sv[5], s4 = sv[6];

    float* obase = out + (size_t)b * (ND * RHW * RHW) + (size_t)h * RHW + w;

    #pragma unroll
    for (int i = 0; i < 32; ++i) {
        int d = d0 + i;
        float pnv = (q == 3 && i == 31) ? 0.f : pn;    // exclude p[128]
        obase[(size_t)d * (RHW * RHW)] = pm + pc + pnv;

        // advance: new p = p[d+2], needs s[d .. d+4]
        float snew = s[(d + 7) * 128 + w];             // s[d+4] (row d+4+3)
        s0 = s1; s1 = s2; s2 = s3; s3 = s4; s4 = snew;
        float pnew = fmaf(G2, s0 + s4, fmaf(G1, s1 + s3, G0 * s2));
        pm = pc; pc = pn; pn = pnew;
    }
}

// ---------------------------------------------------------------------------
extern "C" void kernel_launch(void* const* d_in, const int* in_sizes, int n_in,
                              void* d_out, int out_size) {
    const float* depth = (const float*)d_in[0];   // [8,1,512,512] fp32
    const float* xray  = (const float*)d_in[1];   // [8,1,512,512] fp32
    float* out = (float*)d_out;                   // [8,1,128,128,128] fp32

    (void)in_sizes; (void)n_in; (void)out_size;

    // 68KB dynamic smem for the padded histogram tile (above 48KB default cap)
    cudaFuncSetAttribute(splat_pool_kernel,
                         cudaFuncAttributeMaxDynamicSharedMemorySize,
                         SROWS * 128 * (int)sizeof(float));

    dim3 rgrid(RHW / 4, NB);
    resize_kernel<<<rgrid, 512>>>(depth, xray);

    dim3 sgrid(RHW, NB);
    splat_pool_kernel<<<sgrid, 512, SROWS * 128 * sizeof(float)>>>(out);
}

// round 14
// speedup vs baseline: 1.3811x; 1.3811x over previous
#include <cuda_runtime.h>
#include <cstdint>

// Shapes: depth_map/x_ray [8,1,512,512] fp32 -> out [8,1,128,128,128] fp32
#define NB    8
#define INHW  512
#define RHW   128   // resized H=W
#define ND    128   // depth bins
#define SROWS 134   // histogram rows: depth -3..130 at offset +3

// Intermediate buffers (device globals: allocation-free scratch)
__device__ float g_xr[NB * RHW * RHW];
__device__ int   g_dr[NB * RHW * RHW];   // pre-scaled row offset: (d_idx+3)*128

// ---------------------------------------------------------------------------
// packed f32x2 helpers (ptxas will not auto-fuse; PTX only)
// ---------------------------------------------------------------------------
__device__ __forceinline__ unsigned long long pk2(float v) {
    unsigned long long r;
    asm("mov.b64 %0,{%1,%1};" : "=l"(r) : "f"(v));
    return r;
}
__device__ __forceinline__ ulonglong2 addp(ulonglong2 a, ulonglong2 b) {
    ulonglong2 r;
    asm("add.rn.f32x2 %0,%2,%3;\n\t"
        "add.rn.f32x2 %1,%4,%5;"
        : "=l"(r.x), "=l"(r.y)
        : "l"(a.x), "l"(b.x), "l"(a.y), "l"(b.y));
    return r;
}
__device__ __forceinline__ ulonglong2 fmap(ulonglong2 a, unsigned long long w, ulonglong2 c) {
    ulonglong2 r;
    asm("fma.rn.f32x2 %0,%2,%4,%5;\n\t"
        "fma.rn.f32x2 %1,%3,%4,%6;"
        : "=l"(r.x), "=l"(r.y)
        : "l"(a.x), "l"(a.y), "l"(w), "l"(c.x), "l"(c.y));
    return r;
}
__device__ __forceinline__ ulonglong2 mulp(ulonglong2 a, unsigned long long w) {
    ulonglong2 r;
    asm("mul.rn.f32x2 %0,%2,%3;\n\t"
        "mul.rn.f32x2 %1,%4,%3;"
        : "=l"(r.x), "=l"(r.y)
        : "l"(a.x), "l"(w), "l"(a.y));
    return r;
}

// ---------------------------------------------------------------------------
// Kernel 1: jax.image.resize(bilinear, antialias=True) 512->128 both arrays,
// plus depth->index conversion. Block = (h, b), 256 threads:
//   half = tid>>7 owns 4 of the 8 vertical taps (halves the LDG chain,
//   doubles resident warps); wt = tid&127 is the float4 column group.
// Horizontal pass: half 0 computes depth (-> g_dr pre-scaled row), half 1
// computes x_ray (-> g_xr). Raw triangle weights {1,3,5,7,7,5,3,1}/8,
// normalized by the in-range weight sum (jax edge renormalization).
// ---------------------------------------------------------------------------
__global__ __launch_bounds__(256) void resize_kernel(const float* __restrict__ depth,
                                                     const float* __restrict__ xray) {
    const int tid  = threadIdx.x;
    const int half = tid >> 7;
    const int wt   = tid & 127;
    const int h    = blockIdx.x;
    const int b    = blockIdx.y;

    __shared__ float tmpd[2][INHW];
    __shared__ float tmpx[2][INHW];

    const float RW[8] = {0.125f, 0.375f, 0.625f, 0.875f,
                         0.875f, 0.625f, 0.375f, 0.125f};

    float4 ad = make_float4(0.f, 0.f, 0.f, 0.f);
    float4 ax = make_float4(0.f, 0.f, 0.f, 0.f);

    #pragma unroll
    for (int tt = 0; tt < 4; ++tt) {
        int t = half * 4 + tt;
        int j = 4 * h - 2 + t;                 // input row (uniform per warp)
        if ((unsigned)j >= (unsigned)INHW) continue;
        float wv = RW[t];
        const float4* drow = (const float4*)(depth + ((size_t)b * INHW + j) * INHW);
        const float4* xrow = (const float4*)(xray  + ((size_t)b * INHW + j) * INHW);
        float4 dv = drow[wt];
        float4 xv = xrow[wt];
        ad.x = fmaf(wv, dv.x, ad.x); ad.y = fmaf(wv, dv.y, ad.y);
        ad.z = fmaf(wv, dv.z, ad.z); ad.w = fmaf(wv, dv.w, ad.w);
        ax.x = fmaf(wv, xv.x, ax.x); ax.y = fmaf(wv, xv.y, ax.y);
        ax.z = fmaf(wv, xv.z, ax.z); ax.w = fmaf(wv, xv.w, ax.w);
    }
    ((float4*)tmpd[half])[wt] = ad;
    ((float4*)tmpx[half])[wt] = ax;

    // full vertical in-range weight sum (uniform scalar, no loads)
    float wsv = 0.f;
    #pragma unroll
    for (int t = 0; t < 8; ++t) {
        int j = 4 * h - 2 + t;
        if ((unsigned)j < (unsigned)INHW) wsv += RW[t];
    }
    __syncthreads();

    const float* buf0 = half ? tmpx[0] : tmpd[0];
    const float* buf1 = half ? tmpx[1] : tmpd[1];

    float acc = 0.f, wsh = 0.f;
    #pragma unroll
    for (int t = 0; t < 8; ++t) {
        int c = 4 * wt - 2 + t;                // input col
        if ((unsigned)c < (unsigned)INHW) {
            float wv = RW[t];
            wsh += wv;
            acc = fmaf(wv, buf0[c] + buf1[c], acc);
        }
    }
    float val = acc / (wsv * wsh);

    int idx = (b * RHW + h) * RHW + wt;
    if (half == 0) {
        // d_idx = clip(int((depth/100)*127), 0, 127); store pre-scaled row
        int di = (int)((val / 100.f) * 127.f);
        di = di < 0 ? 0 : (di > ND - 1 ? ND - 1 : di);
        g_dr[idx] = (di + 3) * 128;
    } else {
        g_xr[idx] = val;
    }
}

// ---------------------------------------------------------------------------
// Kernel 2: fused gaussian depth splat + 3x3x3 avg pool (/27, include_pad):
//   s[d][w] = 9-neighbor weighted histogram (3x3 spatial pool folded in)
//   out[d]  = (W7 (*) s)[d]  where W7 = box3 (*) gauss5, /27 folded in,
//   minus exact corrections at d=0 / d=127 for the excluded pool taps
//   p[-1] / p[128]  (p = gauss5 (*) s evaluated only on [0,127] — this is
//   exactly the reference's splat-target clipping + pool zero-pad).
// Block = (h, b), 512 threads.
//   Scatter: threads 0..127 (w), 9 bank-conflict-free smem RMWs each.
//   Gather: thread = (wq = tid&31 -> 4 w's, dq = tid>>5 -> 8 depths);
//   7-row float4 sliding window, packed f32x2 math, LDS.128 in, STG.128 out.
// ---------------------------------------------------------------------------
__global__ __launch_bounds__(512) void splat_pool_kernel(float* __restrict__ out) {
    extern __shared__ float s[];               // [SROWS][128], 68608 B
    __shared__ float sxs[3][130];
    __shared__ int   sdr[3][130];

    const int h   = blockIdx.x;
    const int b   = blockIdx.y;
    const int tid = threadIdx.x;

    // Zero the histogram tile (float4)
    float4* s4 = (float4*)s;
    for (int i = tid; i < SROWS * 128 / 4; i += 512)
        s4[i] = make_float4(0.f, 0.f, 0.f, 0.f);

    // Halo load: 3 rows x 130 cols (zero xv out of range -> harmless RMW)
    if (tid < 3 * 130) {
        int dh = tid / 130, wi = tid - dh * 130;
        int hh = h + dh - 1, ww = wi - 1;
        bool v = ((unsigned)hh < (unsigned)RHW) && ((unsigned)ww < (unsigned)RHW);
        int idx = (b * RHW + (v ? hh : 0)) * RHW + (v ? ww : 0);
        sxs[dh][wi] = v ? g_xr[idx] : 0.f;
        sdr[dh][wi] = v ? g_dr[idx] : 3 * 128;
    }
    __syncthreads();

    // Scatter: unique owner per w column -> no atomics; bank = w%32 always
    if (tid < 128) {
        const int w = tid;
        #pragma unroll
        for (int dh = 0; dh < 3; ++dh) {
            #pragma unroll
            for (int dw = 0; dw < 3; ++dw) {
                float xv = sxs[dh][w + dw];
                int   ro = sdr[dh][w + dw];
                s[ro + w] += xv;
            }
        }
    }
    __syncthreads();

    // 7-tap combined weights (symmetric), 1/27 folded in
    const float e1 = 0.60653065971263342f;     // exp(-0.5)
    const float e2 = 0.13533528323661270f;     // exp(-2)
    const float G0 = 1.f / 27.f, G1 = e1 / 27.f, G2 = e2 / 27.f;
    const unsigned long long W0  = pk2(G0 + 2.f * G1);
    const unsigned long long W1  = pk2(G0 + G1 + G2);
    const unsigned long long W2  = pk2(G1 + G2);
    const unsigned long long W3  = pk2(G2);
    const unsigned long long nG1 = pk2(-G1);
    const unsigned long long nG2 = pk2(-G2);

    const int wq = tid & 31;                   // float4 w-group
    const int dq = tid >> 5;                   // 16 depth groups x 8 depths
    const int d0 = dq << 3;

    const ulonglong2* srow = (const ulonglong2*)s;   // row = 32 ulonglong2

    ulonglong2 v[7];                           // rows d0 .. d0+6 (= s[d0-3..d0+3])
    #pragma unroll
    for (int k = 0; k < 7; ++k) v[k] = srow[(d0 + k) * 32 + wq];

    float* op = out + (size_t)b * (ND * RHW * RHW) + (size_t)h * RHW
                    + (wq << 2) + (size_t)d0 * (RHW * RHW);

    #pragma unroll
    for (int i = 0; i < 8; ++i) {
        // conv: v[0..6] = s[d-3 .. d+3]
        ulonglong2 c = mulp(v[3], W0);
        c = fmap(addp(v[2], v[4]), W1, c);
        c = fmap(addp(v[1], v[5]), W2, c);
        c = fmap(addp(v[0], v[6]), W3, c);
        if (dq == 0 && i == 0) {               // d==0: remove p[-1] = G1*s[0]+G2*s[1]
            c = fmap(v[3], nG1, c);
            c = fmap(v[4], nG2, c);
        }
        if (dq == 15 && i == 7) {              // d==127: remove p[128] = G1*s[127]+G2*s[126]
            c = fmap(v[3], nG1, c);
            c = fmap(v[2], nG2, c);
        }
        *(ulonglong2*)op = c;                  // STG.128, coalesced across warp
        op += RHW * RHW;

        if (i < 7) {
            #pragma unroll
            for (int k = 0; k < 6; ++k) v[k] = v[k + 1];
            v[6] = srow[(d0 + i + 7) * 32 + wq];   // max row 133 = SROWS-1
        }
    }
}

// ---------------------------------------------------------------------------
extern "C" void kernel_launch(void* const* d_in, const int* in_sizes, int n_in,
                              void* d_out, int out_size) {
    const float* depth = (const float*)d_in[0];   // [8,1,512,512] fp32
    const float* xray  = (const float*)d_in[1];   // [8,1,512,512] fp32
    float* out = (float*)d_out;                   // [8,1,128,128,128] fp32

    (void)in_sizes; (void)n_in; (void)out_size;

    cudaFuncSetAttribute(splat_pool_kernel,
                         cudaFuncAttributeMaxDynamicSharedMemorySize,
                         SROWS * 128 * (int)sizeof(float));

    dim3 grid(RHW, NB);
    resize_kernel<<<grid, 256>>>(depth, xray);
    splat_pool_kernel<<<grid, 512, SROWS * 128 * sizeof(float)>>>(out);
}